// round 1
// baseline (speedup 1.0000x reference)
#include <cuda_runtime.h>
#include <cfloat>

#define Bc 8
#define Np 4096
#define C1c 64
#define C2c 128
#define C3c 256

// ---------------- scratch (static __device__, no allocs) ----------------
__device__ float g_X1[Bc * C1c * Np];          // 8 MB
__device__ float g_X2[Bc * C2c * Np];          // 16 MB
__device__ float g_X3[Bc * C3c * Np];          // 32 MB  (F, channel-major)
__device__ float g_Ft[Bc * Np * C3c];          // 32 MB  (F transpose, point-major)
__device__ float g_sq[Bc * Np];
__device__ float g_G[(size_t)Np * Np];         // 64 MB  (per-batch Gram, reused)
__device__ float g_E[Bc * Np * C3c];           // 32 MB  (edge features, point-major)
__device__ float g_pool[Bc * C3c];

// ---------------- conv 1x1 as GEMM: Y[b] = W (Cout x Cin) * X[b] (Cin x N) + bias ----
// tile 64 (cout) x 128 (pts) x 16 (k), 256 threads, 4x8 per thread
template <int L>
__global__ __launch_bounds__(256) void conv_gemm(const float* __restrict__ Xin,
                                                 const float* __restrict__ W,
                                                 const float* __restrict__ bias)
{
    constexpr int Cin  = (L == 0) ? 3  : (L == 1) ? 64  : 128;
    constexpr int Cout = (L == 0) ? 64 : (L == 1) ? 128 : 256;
    const float* X = (L == 0) ? Xin : (L == 1) ? g_X1 : g_X2;
    float*       Y = (L == 0) ? g_X1 : (L == 1) ? g_X2 : g_X3;

    const int b  = blockIdx.z;
    const int m0 = blockIdx.y * 64;
    const int n0 = blockIdx.x * 128;
    const float* Xb = X + (size_t)b * Cin * Np;
    float*       Yb = Y + (size_t)b * Cout * Np;

    __shared__ float Ws[16][64];
    __shared__ float Xs[16][128];

    const int tid = threadIdx.x;
    const int tx = tid & 15;      // 16 groups of 8 pts
    const int ty = tid >> 4;      // 16 groups of 4 couts

    float acc[4][8];
#pragma unroll
    for (int i = 0; i < 4; i++)
#pragma unroll
        for (int j = 0; j < 8; j++) acc[i][j] = 0.f;

    for (int k0 = 0; k0 < Cin; k0 += 16) {
        for (int i = tid; i < 64 * 16; i += 256) {
            int m = i >> 4, k = i & 15;
            Ws[k][m] = (k0 + k < Cin) ? W[(m0 + m) * Cin + k0 + k] : 0.f;
        }
        for (int i = tid; i < 16 * 128; i += 256) {
            int k = i >> 7, n = i & 127;
            Xs[k][n] = (k0 + k < Cin) ? Xb[(size_t)(k0 + k) * Np + n0 + n] : 0.f;
        }
        __syncthreads();
#pragma unroll
        for (int k = 0; k < 16; k++) {
            float a[4], bb[8];
#pragma unroll
            for (int i = 0; i < 4; i++) a[i] = Ws[k][ty * 4 + i];
#pragma unroll
            for (int j = 0; j < 8; j++) bb[j] = Xs[k][tx * 8 + j];
#pragma unroll
            for (int i = 0; i < 4; i++)
#pragma unroll
                for (int j = 0; j < 8; j++) acc[i][j] += a[i] * bb[j];
        }
        __syncthreads();
    }
#pragma unroll
    for (int i = 0; i < 4; i++) {
        float bi = bias[m0 + ty * 4 + i];
#pragma unroll
        for (int j = 0; j < 8; j++)
            Yb[(size_t)(m0 + ty * 4 + i) * Np + n0 + tx * 8 + j] = acc[i][j] + bi;
    }
}

// ---------------- LayerNorm over point axis (per b,channel row) + affine(g[n],be[n]) + relu, in place
template <int L>
__global__ __launch_bounds__(256) void ln_relu(const float* __restrict__ g,
                                               const float* __restrict__ be)
{
    float* X = (L == 0) ? g_X1 : (L == 1) ? g_X2 : g_X3;
    const size_t base = (size_t)blockIdx.x * Np;
    const int tid = threadIdx.x;

    float y[16];
    float s = 0.f;
#pragma unroll
    for (int i = 0; i < 16; i++) {
        y[i] = X[base + tid + i * 256];
        s += y[i];
    }
    __shared__ float red[8];
    __shared__ float smu, svar;
#pragma unroll
    for (int o = 16; o; o >>= 1) s += __shfl_xor_sync(0xffffffffu, s, o);
    if ((tid & 31) == 0) red[tid >> 5] = s;
    __syncthreads();
    if (tid == 0) {
        float t = 0.f;
#pragma unroll
        for (int i = 0; i < 8; i++) t += red[i];
        smu = t * (1.f / Np);
    }
    __syncthreads();
    const float mu = smu;
    float vs = 0.f;
#pragma unroll
    for (int i = 0; i < 16; i++) {
        float d = y[i] - mu;
        vs += d * d;
    }
#pragma unroll
    for (int o = 16; o; o >>= 1) vs += __shfl_xor_sync(0xffffffffu, vs, o);
    if ((tid & 31) == 0) red[tid >> 5] = vs;
    __syncthreads();
    if (tid == 0) {
        float t = 0.f;
#pragma unroll
        for (int i = 0; i < 8; i++) t += red[i];
        svar = t * (1.f / Np);
    }
    __syncthreads();
    const float rstd = rsqrtf(svar + 1e-5f);
#pragma unroll
    for (int i = 0; i < 16; i++) {
        int n = tid + i * 256;
        X[base + n] = fmaxf((y[i] - mu) * rstd * g[n] + be[n], 0.f);
    }
}

// ---------------- transpose X3 [b][c][n] -> Ft [b][n][c] ----------------
__global__ __launch_bounds__(256) void transpose_k()
{
    __shared__ float t[32][33];
    const int b  = blockIdx.z;
    const int n0 = blockIdx.x * 32;
    const int c0 = blockIdx.y * 32;
    const float* Xb = g_X3 + (size_t)b * C3c * Np;
    float*       Fb = g_Ft + (size_t)b * Np * C3c;
    for (int r = threadIdx.y; r < 32; r += 8)
        t[r][threadIdx.x] = Xb[(size_t)(c0 + r) * Np + n0 + threadIdx.x];
    __syncthreads();
    for (int r = threadIdx.y; r < 32; r += 8)
        Fb[(size_t)(n0 + r) * C3c + c0 + threadIdx.x] = t[threadIdx.x][r];
}

// ---------------- sq[b][n] = sum_c F^2 ----------------
__global__ __launch_bounds__(256) void sq_k()
{
    const int b = blockIdx.y;
    const int n = blockIdx.x * 256 + threadIdx.x;
    const float* Xb = g_X3 + (size_t)b * C3c * Np;
    float a = 0.f;
    for (int c = 0; c < C3c; c++) {
        float v = Xb[(size_t)c * Np + n];
        a += v * v;
    }
    g_sq[b * Np + n] = a;
}

// ---------------- Gram: G = F^T F per batch, symmetric (upper-tri tiles + mirror) ----
// 128x128x16 tiles, 256 threads, 8x8 per thread
__global__ __launch_bounds__(256) void gram_k(int b)
{
    int bi = 0, rem = blockIdx.x;
    while (rem >= 32 - bi) { rem -= 32 - bi; bi++; }
    const int bj = bi + rem;
    const int n0 = bi * 128;
    const int m0 = bj * 128;
    const float* F = g_X3 + (size_t)b * C3c * Np;

    __shared__ float As[16][128];
    __shared__ float Bs2[16][128];

    const int tid = threadIdx.x;
    const int tx = tid & 15;   // 8 cols each
    const int ty = tid >> 4;   // 8 rows each

    float acc[8][8];
#pragma unroll
    for (int i = 0; i < 8; i++)
#pragma unroll
        for (int j = 0; j < 8; j++) acc[i][j] = 0.f;

    for (int k0 = 0; k0 < C3c; k0 += 16) {
        for (int i = tid; i < 2048; i += 256) {
            int k = i >> 7, n = i & 127;
            As[k][n]  = F[(size_t)(k0 + k) * Np + n0 + n];
            Bs2[k][n] = F[(size_t)(k0 + k) * Np + m0 + n];
        }
        __syncthreads();
#pragma unroll
        for (int k = 0; k < 16; k++) {
            float a[8], bb[8];
#pragma unroll
            for (int i = 0; i < 8; i++) a[i] = As[k][ty * 8 + i];
#pragma unroll
            for (int j = 0; j < 8; j++) bb[j] = Bs2[k][tx * 8 + j];
#pragma unroll
            for (int i = 0; i < 8; i++)
#pragma unroll
                for (int j = 0; j < 8; j++) acc[i][j] += a[i] * bb[j];
        }
        __syncthreads();
    }
#pragma unroll
    for (int i = 0; i < 8; i++)
#pragma unroll
        for (int j = 0; j < 8; j++)
            g_G[(size_t)(n0 + ty * 8 + i) * Np + m0 + tx * 8 + j] = acc[i][j];
    if (bi != bj) {
#pragma unroll
        for (int i = 0; i < 8; i++)
#pragma unroll
            for (int j = 0; j < 8; j++)
                g_G[(size_t)(m0 + tx * 8 + j) * Np + n0 + ty * 8 + i] = acc[i][j];
    }
}

// ---------------- per-row top-16 smallest of s[m]=sq[m]-2*G[n][m], then gather-max ----
__global__ __launch_bounds__(128) void topk_edge(int b)
{
    const int n   = blockIdx.x;
    const int tid = threadIdx.x;
    const float* sqb = g_sq + (size_t)b * Np;
    const float* Ftb = g_Ft + (size_t)b * Np * C3c;
    float*       Eb  = g_E  + (size_t)b * Np * C3c;
    const float* Grow = g_G + (size_t)n * Np;

    float v[16];
    int   ix[16];
#pragma unroll
    for (int i = 0; i < 16; i++) { v[i] = FLT_MAX; ix[i] = -1; }

    for (int m = tid; m < Np; m += 128) {
        float s = sqb[m] - 2.f * Grow[m];
        if (s < v[15]) {
            int p = 15;
            while (p > 0 && v[p - 1] > s) {
                v[p] = v[p - 1];
                ix[p] = ix[p - 1];
                --p;
            }
            v[p] = s;
            ix[p] = m;
        }
    }

    __shared__ float hv[128];
    __shared__ int   hx[128];
    __shared__ int   knn[16];
    int p = 0;
    for (int r = 0; r < 16; r++) {
        hv[tid] = (p < 16) ? v[p] : FLT_MAX;
        hx[tid] = (p < 16) ? ix[p] : -1;
        __syncthreads();
        for (int o = 64; o > 0; o >>= 1) {
            if (tid < o) {
                if (hv[tid + o] < hv[tid]) {
                    hv[tid] = hv[tid + o];
                    hx[tid] = hx[tid + o];
                }
            }
            __syncthreads();
        }
        int win = hx[0];
        if (tid == 0) knn[r] = win;
        if (p < 16 && ix[p] == win) p++;
        __syncthreads();
    }

    for (int c = tid; c < C3c; c += 128) {
        float mx = -FLT_MAX;
#pragma unroll
        for (int k = 0; k < 16; k++)
            mx = fmaxf(mx, Ftb[(size_t)knn[k] * C3c + c]);
        Eb[(size_t)n * C3c + c] = mx;
    }
}

// ---------------- mean pool over points ----------------
__global__ __launch_bounds__(256) void pool_k()
{
    const int b = blockIdx.x;
    const int c = threadIdx.x;
    const float* Eb = g_E + (size_t)b * Np * C3c;
    float a = 0.f;
    for (int n = 0; n < Np; n++) a += Eb[(size_t)n * C3c + c];
    g_pool[b * C3c + c] = a * (1.f / Np);
}

// ---------------- tiny MLP 256->128->64->1 for all 8 batches ----------------
__global__ __launch_bounds__(256) void mlp_k(const float* __restrict__ gw0, const float* __restrict__ gb0,
                                             const float* __restrict__ gw1, const float* __restrict__ gb1,
                                             const float* __restrict__ gw2, const float* __restrict__ gb2,
                                             float* __restrict__ out)
{
    __shared__ float h1[8][128];
    __shared__ float h2[8][64];
    const int tid = threadIdx.x;

    for (int idx = tid; idx < 8 * 128; idx += 256) {
        int b = idx >> 7, j = idx & 127;
        float s = gb0[j];
        for (int i = 0; i < 256; i++) s += g_pool[b * 256 + i] * gw0[j * 256 + i];
        h1[b][j] = fmaxf(s, 0.f);
    }
    __syncthreads();
    for (int idx = tid; idx < 8 * 64; idx += 256) {
        int b = idx >> 6, j = idx & 63;
        float s = gb1[j];
        for (int i = 0; i < 128; i++) s += h1[b][i] * gw1[j * 128 + i];
        h2[b][j] = fmaxf(s, 0.f);
    }
    __syncthreads();
    if (tid < 8) {
        float s = gb2[0];
        for (int i = 0; i < 64; i++) s += h2[tid][i] * gw2[i];
        out[tid] = s;
    }
}

// ---------------- launch ----------------
extern "C" void kernel_launch(void* const* d_in, const int* in_sizes, int n_in,
                              void* d_out, int out_size)
{
    (void)in_sizes; (void)n_in; (void)out_size;
    const float* pc  = (const float*)d_in[0];
    const float* w0  = (const float*)d_in[1];
    const float* b0  = (const float*)d_in[2];
    const float* g0  = (const float*)d_in[3];
    const float* be0 = (const float*)d_in[4];
    const float* w1  = (const float*)d_in[5];
    const float* b1  = (const float*)d_in[6];
    const float* g1  = (const float*)d_in[7];
    const float* be1 = (const float*)d_in[8];
    const float* w2  = (const float*)d_in[9];
    const float* b2  = (const float*)d_in[10];
    const float* g2  = (const float*)d_in[11];
    const float* be2 = (const float*)d_in[12];
    const float* gw0 = (const float*)d_in[13];
    const float* gb0 = (const float*)d_in[14];
    const float* gw1 = (const float*)d_in[15];
    const float* gb1 = (const float*)d_in[16];
    const float* gw2 = (const float*)d_in[17];
    const float* gb2 = (const float*)d_in[18];
    float* out = (float*)d_out;

    conv_gemm<0><<<dim3(32, 1, Bc), 256>>>(pc, w0, b0);
    ln_relu<0><<<Bc * C1c, 256>>>(g0, be0);
    conv_gemm<1><<<dim3(32, 2, Bc), 256>>>(nullptr, w1, b1);
    ln_relu<1><<<Bc * C2c, 256>>>(g1, be1);
    conv_gemm<2><<<dim3(32, 4, Bc), 256>>>(nullptr, w2, b2);
    ln_relu<2><<<Bc * C3c, 256>>>(g2, be2);

    transpose_k<<<dim3(Np / 32, C3c / 32, Bc), dim3(32, 8)>>>();
    sq_k<<<dim3(Np / 256, Bc), 256>>>();

    for (int b = 0; b < Bc; b++) {
        gram_k<<<528, 256>>>(b);        // 32*33/2 upper-triangle tiles
        topk_edge<<<Np, 128>>>(b);
    }

    pool_k<<<Bc, 256>>>();
    mlp_k<<<1, 256>>>(gw0, gb0, gw1, gb1, gw2, gb2, out);
}

// round 2
// speedup vs baseline: 1.4032x; 1.4032x over previous
#include <cuda_runtime.h>
#include <cfloat>

#define Bc 8
#define Np 4096
#define C1c 64
#define C2c 128
#define C3c 256

// ---------------- scratch (static __device__, no allocs) ----------------
__device__ float g_X1[Bc * C1c * Np];                 // 8 MB
__device__ float g_X2[Bc * C2c * Np];                 // 16 MB
__device__ float g_X3[Bc * C3c * Np];                 // 32 MB  (F, channel-major)
__device__ float g_Ft[Bc * Np * C3c];                 // 32 MB  (F transpose, point-major)
__device__ float g_sq[Bc * Np];
__device__ float g_G[(size_t)Bc * Np * Np];           // 512 MB (all-batch Gram)
__device__ float g_E[Bc * Np * C3c];                  // 32 MB  (edge features, point-major)
__device__ float g_poolp[Bc * 16 * C3c];              // pooling partials

// ---------------- conv 1x1 as GEMM: Y[b] = W (Cout x Cin) * X[b] (Cin x N) + bias ----
template <int L>
__global__ __launch_bounds__(256) void conv_gemm(const float* __restrict__ Xin,
                                                 const float* __restrict__ W,
                                                 const float* __restrict__ bias)
{
    constexpr int Cin  = (L == 0) ? 3  : (L == 1) ? 64  : 128;
    const float* X = (L == 0) ? Xin : (L == 1) ? g_X1 : g_X2;
    float*       Y = (L == 0) ? g_X1 : (L == 1) ? g_X2 : g_X3;

    const int b  = blockIdx.z;
    const int m0 = blockIdx.y * 64;
    const int n0 = blockIdx.x * 128;
    const float* Xb = X + (size_t)b * Cin * Np;
    float*       Yb = Y + (size_t)b * ((L == 0) ? 64 : (L == 1) ? 128 : 256) * Np;

    __shared__ float Ws[16][64];
    __shared__ float Xs[16][128];

    const int tid = threadIdx.x;
    const int tx = tid & 15;
    const int ty = tid >> 4;

    float acc[4][8];
#pragma unroll
    for (int i = 0; i < 4; i++)
#pragma unroll
        for (int j = 0; j < 8; j++) acc[i][j] = 0.f;

    for (int k0 = 0; k0 < Cin; k0 += 16) {
        for (int i = tid; i < 64 * 16; i += 256) {
            int m = i >> 4, k = i & 15;
            Ws[k][m] = (k0 + k < Cin) ? W[(m0 + m) * Cin + k0 + k] : 0.f;
        }
        for (int i = tid; i < 16 * 128; i += 256) {
            int k = i >> 7, n = i & 127;
            Xs[k][n] = (k0 + k < Cin) ? Xb[(size_t)(k0 + k) * Np + n0 + n] : 0.f;
        }
        __syncthreads();
#pragma unroll
        for (int k = 0; k < 16; k++) {
            float a[4], bb[8];
#pragma unroll
            for (int i = 0; i < 4; i++) a[i] = Ws[k][ty * 4 + i];
#pragma unroll
            for (int j = 0; j < 8; j++) bb[j] = Xs[k][tx * 8 + j];
#pragma unroll
            for (int i = 0; i < 4; i++)
#pragma unroll
                for (int j = 0; j < 8; j++) acc[i][j] += a[i] * bb[j];
        }
        __syncthreads();
    }
#pragma unroll
    for (int i = 0; i < 4; i++) {
        float bi = bias[m0 + ty * 4 + i];
#pragma unroll
        for (int j = 0; j < 8; j++)
            Yb[(size_t)(m0 + ty * 4 + i) * Np + n0 + tx * 8 + j] = acc[i][j] + bi;
    }
}

// ---------------- LayerNorm over point axis + affine(g[n],be[n]) + relu, in place ----
template <int L>
__global__ __launch_bounds__(256) void ln_relu(const float* __restrict__ g,
                                               const float* __restrict__ be)
{
    float* X = (L == 0) ? g_X1 : (L == 1) ? g_X2 : g_X3;
    const size_t base = (size_t)blockIdx.x * Np;
    const int tid = threadIdx.x;

    float y[16];
    float s = 0.f;
#pragma unroll
    for (int i = 0; i < 16; i++) {
        y[i] = X[base + tid + i * 256];
        s += y[i];
    }
    __shared__ float red[8];
    __shared__ float smu, svar;
#pragma unroll
    for (int o = 16; o; o >>= 1) s += __shfl_xor_sync(0xffffffffu, s, o);
    if ((tid & 31) == 0) red[tid >> 5] = s;
    __syncthreads();
    if (tid == 0) {
        float t = 0.f;
#pragma unroll
        for (int i = 0; i < 8; i++) t += red[i];
        smu = t * (1.f / Np);
    }
    __syncthreads();
    const float mu = smu;
    float vs = 0.f;
#pragma unroll
    for (int i = 0; i < 16; i++) {
        float d = y[i] - mu;
        vs += d * d;
    }
#pragma unroll
    for (int o = 16; o; o >>= 1) vs += __shfl_xor_sync(0xffffffffu, vs, o);
    if ((tid & 31) == 0) red[tid >> 5] = vs;
    __syncthreads();
    if (tid == 0) {
        float t = 0.f;
#pragma unroll
        for (int i = 0; i < 8; i++) t += red[i];
        svar = t * (1.f / Np);
    }
    __syncthreads();
    const float rstd = rsqrtf(svar + 1e-5f);
#pragma unroll
    for (int i = 0; i < 16; i++) {
        int n = tid + i * 256;
        X[base + n] = fmaxf((y[i] - mu) * rstd * g[n] + be[n], 0.f);
    }
}

// ---------------- transpose X3 [b][c][n] -> Ft [b][n][c] ----------------
__global__ __launch_bounds__(256) void transpose_k()
{
    __shared__ float t[32][33];
    const int b  = blockIdx.z;
    const int n0 = blockIdx.x * 32;
    const int c0 = blockIdx.y * 32;
    const float* Xb = g_X3 + (size_t)b * C3c * Np;
    float*       Fb = g_Ft + (size_t)b * Np * C3c;
    for (int r = threadIdx.y; r < 32; r += 8)
        t[r][threadIdx.x] = Xb[(size_t)(c0 + r) * Np + n0 + threadIdx.x];
    __syncthreads();
    for (int r = threadIdx.y; r < 32; r += 8)
        Fb[(size_t)(n0 + r) * C3c + c0 + threadIdx.x] = t[threadIdx.x][r];
}

// ---------------- sq[b][n] = sum_c F^2 ----------------
__global__ __launch_bounds__(256) void sq_k()
{
    const int b = blockIdx.y;
    const int n = blockIdx.x * 256 + threadIdx.x;
    const float* Xb = g_X3 + (size_t)b * C3c * Np;
    float a = 0.f;
    for (int c = 0; c < C3c; c++) {
        float v = Xb[(size_t)c * Np + n];
        a += v * v;
    }
    g_sq[b * Np + n] = a;
}

// ---------------- Gram v2: all batches, K-tile 32, float4 frags, symmetric ----
__global__ __launch_bounds__(256) void gram_k()
{
    const int b = blockIdx.y;
    int bi = 0, rem = blockIdx.x;
    while (rem >= 32 - bi) { rem -= 32 - bi; bi++; }
    const int bj = bi + rem;
    const int n0 = bi * 128;
    const int m0 = bj * 128;
    const float* F = g_X3 + (size_t)b * C3c * Np;
    float* Gb = g_G + (size_t)b * Np * Np;

    __shared__ float4 As4[32][32];   // [k][c4] : 128 floats per k-row
    __shared__ float4 Bs4[32][32];

    const int tid = threadIdx.x;
    const int tx = tid & 15;
    const int ty = tid >> 4;

    float acc[8][8];
#pragma unroll
    for (int i = 0; i < 8; i++)
#pragma unroll
        for (int j = 0; j < 8; j++) acc[i][j] = 0.f;

    for (int k0 = 0; k0 < C3c; k0 += 32) {
        for (int i = tid; i < 1024; i += 256) {
            int k  = i >> 5;
            int c4 = i & 31;
            As4[k][c4] = ((const float4*)(F + (size_t)(k0 + k) * Np + n0))[c4];
            Bs4[k][c4] = ((const float4*)(F + (size_t)(k0 + k) * Np + m0))[c4];
        }
        __syncthreads();
#pragma unroll
        for (int k = 0; k < 32; k++) {
            float4 a0 = As4[k][ty * 2], a1 = As4[k][ty * 2 + 1];
            float4 b0 = Bs4[k][tx * 2], b1 = Bs4[k][tx * 2 + 1];
            float a[8] = {a0.x, a0.y, a0.z, a0.w, a1.x, a1.y, a1.z, a1.w};
            float bb[8] = {b0.x, b0.y, b0.z, b0.w, b1.x, b1.y, b1.z, b1.w};
#pragma unroll
            for (int i = 0; i < 8; i++)
#pragma unroll
                for (int j = 0; j < 8; j++) acc[i][j] += a[i] * bb[j];
        }
        __syncthreads();
    }
#pragma unroll
    for (int i = 0; i < 8; i++)
#pragma unroll
        for (int j = 0; j < 8; j++)
            Gb[(size_t)(n0 + ty * 8 + i) * Np + m0 + tx * 8 + j] = acc[i][j];
    if (bi != bj) {
#pragma unroll
        for (int i = 0; i < 8; i++)
#pragma unroll
            for (int j = 0; j < 8; j++)
                Gb[(size_t)(m0 + tx * 8 + j) * Np + n0 + ty * 8 + i] = acc[i][j];
    }
}

// ---------------- topk v2: u64 keys, warp-shuffle selection, all batches ----
// key = (sortable(s) << 32) | m  -> min key == min value, ties -> min index (jax match)
__device__ __forceinline__ unsigned long long pack_key(float s, int m)
{
    unsigned int u = __float_as_uint(s);
    u ^= (u >> 31) ? 0xFFFFFFFFu : 0x80000000u;
    return ((unsigned long long)u << 32) | (unsigned int)m;
}

__global__ __launch_bounds__(128) void topk_edge()
{
    const int b   = blockIdx.y;
    const int n   = blockIdx.x;
    const int tid = threadIdx.x;
    const float4* sq4  = (const float4*)(g_sq + (size_t)b * Np);
    const float4* G4   = (const float4*)(g_G + (size_t)b * Np * Np + (size_t)n * Np);
    const float* Ftb   = g_Ft + (size_t)b * Np * C3c;
    float*       Eb    = g_E  + (size_t)b * Np * C3c;

    unsigned long long v[16];
#pragma unroll
    for (int i = 0; i < 16; i++) v[i] = 0xFFFFFFFFFFFFFFFFull;

    for (int m4 = tid; m4 < Np / 4; m4 += 128) {
        float4 g = G4[m4];
        float4 q = sq4[m4];
        float s0 = q.x - 2.f * g.x;
        float s1 = q.y - 2.f * g.y;
        float s2 = q.z - 2.f * g.z;
        float s3 = q.w - 2.f * g.w;
        unsigned long long ks[4] = {pack_key(s0, m4 * 4), pack_key(s1, m4 * 4 + 1),
                                    pack_key(s2, m4 * 4 + 2), pack_key(s3, m4 * 4 + 3)};
#pragma unroll
        for (int j = 0; j < 4; j++) {
            unsigned long long k = ks[j];
            if (k < v[15]) {
                int p = 15;
                while (p > 0 && v[p - 1] > k) { v[p] = v[p - 1]; --p; }
                v[p] = k;
            }
        }
    }

    __shared__ unsigned long long wmin[4];
    int nbr[16];
    int p = 0;
    const int lane = tid & 31;
    const int wid  = tid >> 5;
    for (int r = 0; r < 16; r++) {
        unsigned long long k = (p < 16) ? v[p] : 0xFFFFFFFFFFFFFFFFull;
#pragma unroll
        for (int o = 16; o; o >>= 1) {
            unsigned long long other = __shfl_xor_sync(0xffffffffu, k, o);
            if (other < k) k = other;
        }
        if (lane == 0) wmin[wid] = k;
        __syncthreads();
        unsigned long long bm = wmin[0];
        if (wmin[1] < bm) bm = wmin[1];
        if (wmin[2] < bm) bm = wmin[2];
        if (wmin[3] < bm) bm = wmin[3];
        nbr[r] = (int)(bm & 0xFFFFFFFFu);
        if (p < 16 && v[p] == bm) p++;
        __syncthreads();
    }

    for (int c = tid; c < C3c; c += 128) {
        float mx = -FLT_MAX;
#pragma unroll
        for (int k = 0; k < 16; k++)
            mx = fmaxf(mx, Ftb[(size_t)nbr[k] * C3c + c]);
        Eb[(size_t)n * C3c + c] = mx;
    }
}

// ---------------- pooling partials: 16 chunks per batch (deterministic) ----
__global__ __launch_bounds__(256) void pool1_k()
{
    const int b  = blockIdx.y;
    const int ch = blockIdx.x;
    const int c  = threadIdx.x;
    const float* Eb = g_E + (size_t)b * Np * C3c;
    float a = 0.f;
    for (int n = ch * 256; n < (ch + 1) * 256; n++)
        a += Eb[(size_t)n * C3c + c];
    g_poolp[(b * 16 + ch) * C3c + c] = a;
}

// ---------------- tiny MLP 256->128->64->1 (sums pooling partials first) ----
__global__ __launch_bounds__(256) void mlp_k(const float* __restrict__ gw0, const float* __restrict__ gb0,
                                             const float* __restrict__ gw1, const float* __restrict__ gb1,
                                             const float* __restrict__ gw2, const float* __restrict__ gb2,
                                             float* __restrict__ out)
{
    __shared__ float pooled[8][256];
    __shared__ float h1[8][128];
    __shared__ float h2[8][64];
    const int tid = threadIdx.x;

    for (int idx = tid; idx < 8 * 256; idx += 256) {
        int b = idx >> 8, c = idx & 255;
        float s = 0.f;
        for (int ch = 0; ch < 16; ch++) s += g_poolp[(b * 16 + ch) * C3c + c];
        pooled[b][c] = s * (1.f / Np);
    }
    __syncthreads();
    for (int idx = tid; idx < 8 * 128; idx += 256) {
        int b = idx >> 7, j = idx & 127;
        float s = gb0[j];
        for (int i = 0; i < 256; i++) s += pooled[b][i] * gw0[j * 256 + i];
        h1[b][j] = fmaxf(s, 0.f);
    }
    __syncthreads();
    for (int idx = tid; idx < 8 * 64; idx += 256) {
        int b = idx >> 6, j = idx & 63;
        float s = gb1[j];
        for (int i = 0; i < 128; i++) s += h1[b][i] * gw1[j * 128 + i];
        h2[b][j] = fmaxf(s, 0.f);
    }
    __syncthreads();
    if (tid < 8) {
        float s = gb2[0];
        for (int i = 0; i < 64; i++) s += h2[tid][i] * gw2[i];
        out[tid] = s;
    }
}

// ---------------- launch ----------------
extern "C" void kernel_launch(void* const* d_in, const int* in_sizes, int n_in,
                              void* d_out, int out_size)
{
    (void)in_sizes; (void)n_in; (void)out_size;
    const float* pc  = (const float*)d_in[0];
    const float* w0  = (const float*)d_in[1];
    const float* b0  = (const float*)d_in[2];
    const float* g0  = (const float*)d_in[3];
    const float* be0 = (const float*)d_in[4];
    const float* w1  = (const float*)d_in[5];
    const float* b1  = (const float*)d_in[6];
    const float* g1  = (const float*)d_in[7];
    const float* be1 = (const float*)d_in[8];
    const float* w2  = (const float*)d_in[9];
    const float* b2  = (const float*)d_in[10];
    const float* g2  = (const float*)d_in[11];
    const float* be2 = (const float*)d_in[12];
    const float* gw0 = (const float*)d_in[13];
    const float* gb0 = (const float*)d_in[14];
    const float* gw1 = (const float*)d_in[15];
    const float* gb1 = (const float*)d_in[16];
    const float* gw2 = (const float*)d_in[17];
    const float* gb2 = (const float*)d_in[18];
    float* out = (float*)d_out;

    conv_gemm<0><<<dim3(32, 1, Bc), 256>>>(pc, w0, b0);
    ln_relu<0><<<Bc * C1c, 256>>>(g0, be0);
    conv_gemm<1><<<dim3(32, 2, Bc), 256>>>(nullptr, w1, b1);
    ln_relu<1><<<Bc * C2c, 256>>>(g1, be1);
    conv_gemm<2><<<dim3(32, 4, Bc), 256>>>(nullptr, w2, b2);
    ln_relu<2><<<Bc * C3c, 256>>>(g2, be2);

    transpose_k<<<dim3(Np / 32, C3c / 32, Bc), dim3(32, 8)>>>();
    sq_k<<<dim3(Np / 256, Bc), 256>>>();

    gram_k<<<dim3(528, Bc), 256>>>();      // all batches, upper-triangle tiles
    topk_edge<<<dim3(Np, Bc), 128>>>();    // all batches

    pool1_k<<<dim3(16, Bc), 256>>>();
    mlp_k<<<1, 256>>>(gw0, gb0, gw1, gb1, gw2, gb2, out);
}